// round 6
// baseline (speedup 1.0000x reference)
#include <cuda_runtime.h>
#include <math.h>
#include <stdint.h>

#define NROWS 8192
#define NHALF 4096
#define DIN   512
#define DF    64      // feature dim padded (50 -> 64, zeros)
#define DOUT  50
#define HID   10
#define BM    128
#define BN    128
#define KC    32      // phase-1 k-chunk (floats)
#define NB    (NROWS/BM)   // 64
#define NCHUNK (DIN/KC)    // 16
#define LDF   129     // Fea tile lead dim ([k][row/col], padded)
#define NT    512     // threads per CTA

// smem float offsets
#define OFF_A0  0
#define OFF_B0  4096
#define OFF_A1  8192
#define OFF_B1  12288
#define OFF_FA  16384                     // Fea A tile [64][129]
#define OFF_FB  (OFF_FA + DF*LDF)         // Fea B tile [64][129]
#define SMEM_FLOATS (OFF_FB + DF*LDF)     // 32896
#define SMEM_BYTES  (SMEM_FLOATS * 4)     // 131,584 B

// -------- scratch (no dynamic allocation allowed) --------
__device__ float  g_Xcat[NROWS*DIN];     // tf32-rounded concat(Xs,Xt)
__device__ float  g_Fea [NROWS*DF];      // padded features (fp32)
__device__ float  g_onorm[NROWS];        // norms of ROUNDED originals
__device__ float  g_fnorm[NROWS];
__device__ double g_acc[4];              // Sx, Sy, Smixed(2*sumKxy), Sdiag_xy
__device__ float  g_par[3];              // ep, 1/sigma, 1/sigma0

__device__ __forceinline__ float softplus_f(float x){
    return fmaxf(x, 0.f) + log1pf(expf(-fabsf(x)));
}

// exp(-x) for x >= 0, FMA-pipe only (no MUFU). ~3e-7 relative error.
__device__ __forceinline__ float exp_neg(float x){
    float t = x * -1.4426950408889634f;
    t = fmaxf(t, -125.f);
    float fn = t + 12582912.f;                   // 2^23 + 2^22 round magic
    int   ni = __float_as_int(fn) - 0x4B400000;
    float r  = t - (fn - 12582912.f);
    float p  = 1.5403530393e-4f;
    p = fmaf(p, r, 1.3333558146e-3f);
    p = fmaf(p, r, 9.6181291076e-3f);
    p = fmaf(p, r, 5.5504108665e-2f);
    p = fmaf(p, r, 2.4022650696e-1f);
    p = fmaf(p, r, 6.9314718056e-1f);
    p = fmaf(p, r, 1.0f);
    return __int_as_float(__float_as_int(p) + (ni << 23));
}

__device__ __forceinline__ void cp16(float* dst, const float* src){
    uint32_t d = (uint32_t)__cvta_generic_to_shared(dst);
    asm volatile("cp.async.cg.shared.global [%0], [%1], 16;\n"
                 :: "r"(d), "l"(src) : "memory");
}
__device__ __forceinline__ void cp_commit(){
    asm volatile("cp.async.commit_group;\n" ::: "memory");
}

// ---------------- init ----------------
__global__ void init_kernel(const float* __restrict__ eps,
                            const float* __restrict__ sig,
                            const float* __restrict__ sig0){
    if (threadIdx.x == 0){
        g_par[0] = 1.f / (1.f + expf(-eps[0]));
        g_par[1] = 1.f / (sig[0]  * sig[0]);
        g_par[2] = 1.f / (sig0[0] * sig0[0]);
        g_acc[0] = 0.0; g_acc[1] = 0.0; g_acc[2] = 0.0; g_acc[3] = 0.0;
    }
}

// ---------------- featurize: warp per row ----------------
__global__ __launch_bounds__(256)
void feat_kernel(const float* __restrict__ Xs, const float* __restrict__ Xt,
                 const float* __restrict__ W1, const float* __restrict__ b1,
                 const float* __restrict__ W2, const float* __restrict__ b2,
                 const float* __restrict__ W3, const float* __restrict__ b3,
                 const float* __restrict__ W4, const float* __restrict__ b4)
{
    __shared__ float sW1[DIN*HID];
    __shared__ float sW2[HID*HID], sW3[HID*HID], sW4[HID*DOUT];
    __shared__ float sb1[HID], sb2[HID], sb3[HID], sb4[DOUT];
    int tid = threadIdx.x;
    for (int i = tid; i < DIN*HID; i += 256) sW1[i] = W1[i];
    for (int i = tid; i < HID*HID; i += 256){ sW2[i] = W2[i]; sW3[i] = W3[i]; }
    for (int i = tid; i < HID*DOUT; i += 256) sW4[i] = W4[i];
    if (tid < HID){ sb1[tid] = b1[tid]; sb2[tid] = b2[tid]; sb3[tid] = b3[tid]; }
    if (tid < DOUT) sb4[tid] = b4[tid];
    __syncthreads();

    int warp = tid >> 5, lane = tid & 31;
    int row = blockIdx.x * 8 + warp;
    if (row >= NROWS) return;
    const float* src = (row < NHALF) ? (Xs + (size_t)row * DIN)
                                     : (Xt + (size_t)(row - NHALF) * DIN);
    float acc[HID];
    #pragma unroll
    for (int o = 0; o < HID; o++) acc[o] = 0.f;
    float on = 0.f;
    for (int k = lane; k < DIN; k += 32){
        float x = src[k];
        // tf32-round (rna) ONCE; Gram and norms use the rounded value consistently,
        // so HMMA's mantissa truncation is lossless and Do is exact-for-rounded-data.
        uint32_t xr; asm("cvt.rna.tf32.f32 %0, %1;" : "=r"(xr) : "f"(x));
        float xf = __uint_as_float(xr);
        g_Xcat[(size_t)row * DIN + k] = xf;
        on += xf * xf;
        #pragma unroll
        for (int o = 0; o < HID; o++) acc[o] += x * sW1[k*HID + o];
    }
    #pragma unroll
    for (int off = 16; off; off >>= 1){
        on += __shfl_xor_sync(0xffffffffu, on, off);
        #pragma unroll
        for (int o = 0; o < HID; o++)
            acc[o] += __shfl_xor_sync(0xffffffffu, acc[o], off);
    }
    if (lane == 0) g_onorm[row] = on;

    float h1[HID], h2[HID], h3[HID];
    #pragma unroll
    for (int o = 0; o < HID; o++) h1[o] = softplus_f(acc[o] + sb1[o]);
    #pragma unroll
    for (int o = 0; o < HID; o++){
        float t = sb2[o];
        #pragma unroll
        for (int p = 0; p < HID; p++) t += h1[p] * sW2[p*HID + o];
        h2[o] = softplus_f(t);
    }
    #pragma unroll
    for (int o = 0; o < HID; o++){
        float t = sb3[o];
        #pragma unroll
        for (int p = 0; p < HID; p++) t += h2[p] * sW3[p*HID + o];
        h3[o] = softplus_f(t);
    }
    float fn = 0.f;
    for (int c = lane; c < DF; c += 32){
        float v = 0.f;
        if (c < DOUT){
            v = sb4[c];
            #pragma unroll
            for (int p = 0; p < HID; p++) v += h3[p] * sW4[p*DOUT + c];
        }
        g_Fea[(size_t)row * DF + c] = v;
        fn += v * v;
    }
    #pragma unroll
    for (int off = 16; off; off >>= 1)
        fn += __shfl_xor_sync(0xffffffffu, fn, off);
    if (lane == 0) g_fnorm[row] = fn;
}

// ---------------- fused pairwise kernel (merged phases, 512 thr) ----------------
__global__ __launch_bounds__(NT, 1)
void pair_kernel(){
    int bj = blockIdx.x, bi = blockIdx.y;
    if (bj < bi) return;                       // upper-triangle tiles only
    extern __shared__ float smem[];

    const int tid  = threadIdx.x;
    const int lane = tid & 31, warp = tid >> 5;
    const int gid  = lane >> 2, tig = lane & 3;
    const int warpM = warp & 3, warpN = warp >> 2;   // 4 x 4 warp grid
    const int rw = warpM * 32;                 // warp row base (local)
    const int cw = warpN * 32;                 // warp col base (local)
    const int rowBase = bi * BM, colBase = bj * BN;

    // Both Grams accumulate with IDENTICAL thread ownership:
    // rows {rw+mi*16+rr*8+gid}, cols {cw+ni*8+tig*2+cc}
    float acc[2][4][4];                        // original-space (tensor)
    float fac[2][4][4];                        // feature-space (FFMA, overlapped)
    #pragma unroll
    for (int mi = 0; mi < 2; mi++)
        #pragma unroll
        for (int ni = 0; ni < 4; ni++)
            #pragma unroll
            for (int r = 0; r < 4; r++){ acc[mi][ni][r] = 0.f; fac[mi][ni][r] = 0.f; }

    // prefetch chunks 0 and 1 (SW128-style swizzle: granule g ^= row&7)
    #pragma unroll
    for (int st = 0; st < 2; st++){
        float* bA = smem + (st ? OFF_A1 : OFF_A0);
        float* bB = smem + (st ? OFF_B1 : OFF_B0);
        int kb = st * KC;
        #pragma unroll
        for (int i = 0; i < 2; i++){
            int idx = tid + i * NT;            // 1024 16B-slots per tile
            int r = idx >> 3, g = idx & 7;
            int sw = r*32 + (((g ^ (r & 7)) << 2));
            cp16(bA + sw, &g_Xcat[(size_t)(rowBase + r)*DIN + kb + (g << 2)]);
            cp16(bB + sw, &g_Xcat[(size_t)(colBase + r)*DIN + kb + (g << 2)]);
        }
        cp_commit();
    }

    // load Fea tiles into [k][row] layout (one-time): FA for rows, FB for cols
    {
        float* FA = smem + OFF_FA;
        float* FB = smem + OFF_FB;
        #pragma unroll
        for (int i = 0; i < 16; i++){          // 8192 elements / 512 threads
            int idx = tid + i * NT;
            int r = idx >> 6, k = idx & 63;    // coalesced global read
            FA[k*LDF + r] = g_Fea[(size_t)(rowBase + r)*DF + k];
            FB[k*LDF + r] = g_Fea[(size_t)(colBase + r)*DF + k];
        }
    }

    for (int c = 0; c < NCHUNK; c++){
        if (c < NCHUNK - 1) asm volatile("cp.async.wait_group 1;\n" ::: "memory");
        else                asm volatile("cp.async.wait_group 0;\n" ::: "memory");
        __syncthreads();

        const float* Ash = smem + ((c & 1) ? OFF_A1 : OFF_A0);
        const float* Bsh = smem + ((c & 1) ? OFF_B1 : OFF_B0);
        const float* FA  = smem + OFF_FA;
        const float* FB  = smem + OFF_FB;

        #pragma unroll
        for (int ks8 = 0; ks8 < 4; ks8++){
            const int ks = ks8 * 8;
            const int ga = ks >> 2, gb = ga + 1;
            const int ca = ((ga ^ gid) << 2) + tig;
            const int cb = ((gb ^ gid) << 2) + tig;
            uint32_t bfr[4][2];
            #pragma unroll
            for (int ni = 0; ni < 4; ni++){
                int rb = (cw + ni*8 + gid) * 32;
                bfr[ni][0] = __float_as_uint(Bsh[rb + ca]);
                bfr[ni][1] = __float_as_uint(Bsh[rb + cb]);
            }
            #pragma unroll
            for (int mi = 0; mi < 2; mi++){
                int r0 = (rw + mi*16 +     gid) * 32;
                int r1 = (rw + mi*16 + 8 + gid) * 32;
                uint32_t a0 = __float_as_uint(Ash[r0 + ca]);
                uint32_t a1 = __float_as_uint(Ash[r1 + ca]);
                uint32_t a2 = __float_as_uint(Ash[r0 + cb]);
                uint32_t a3 = __float_as_uint(Ash[r1 + cb]);
                #pragma unroll
                for (int ni = 0; ni < 4; ni++){
                    asm volatile(
                        "mma.sync.aligned.m16n8k8.row.col.f32.tf32.tf32.f32 "
                        "{%0,%1,%2,%3}, {%4,%5,%6,%7}, {%8,%9}, {%0,%1,%2,%3};\n"
                        : "+f"(acc[mi][ni][0]), "+f"(acc[mi][ni][1]),
                          "+f"(acc[mi][ni][2]), "+f"(acc[mi][ni][3])
                        : "r"(a0), "r"(a1), "r"(a2), "r"(a3),
                          "r"(bfr[ni][0]), "r"(bfr[ni][1]));
                }
            }

            // ---- overlapped phase-2 slice: feature k = c*4 + ks8 (FMA pipe) ----
            {
                const int k = c*4 + ks8;
                float a2v[4], b2v[8];
                #pragma unroll
                for (int mi = 0; mi < 2; mi++)
                    #pragma unroll
                    for (int rr = 0; rr < 2; rr++)
                        a2v[mi*2+rr] = FA[k*LDF + rw + mi*16 + rr*8 + gid];
                #pragma unroll
                for (int ni = 0; ni < 4; ni++)
                    #pragma unroll
                    for (int cc = 0; cc < 2; cc++)
                        b2v[ni*2+cc] = FB[k*LDF + cw + ni*8 + tig*2 + cc];
                #pragma unroll
                for (int mi = 0; mi < 2; mi++)
                    #pragma unroll
                    for (int ni = 0; ni < 4; ni++)
                        #pragma unroll
                        for (int rr = 0; rr < 2; rr++)
                            #pragma unroll
                            for (int cc = 0; cc < 2; cc++)
                                fac[mi][ni][rr*2+cc] +=
                                    a2v[mi*2+rr] * b2v[ni*2+cc];
            }
        }
        __syncthreads();     // all warps done reading buf[c&1] before refill

        if (c + 2 < NCHUNK){
            float* bA = smem + ((c & 1) ? OFF_A1 : OFF_A0);
            float* bB = smem + ((c & 1) ? OFF_B1 : OFF_B0);
            int kb = (c + 2) * KC;
            #pragma unroll
            for (int i = 0; i < 2; i++){
                int idx = tid + i * NT;
                int r = idx >> 3, g = idx & 7;
                int sw = r*32 + (((g ^ (r & 7)) << 2));
                cp16(bA + sw, &g_Xcat[(size_t)(rowBase + r)*DIN + kb + (g << 2)]);
                cp16(bB + sw, &g_Xcat[(size_t)(colBase + r)*DIN + kb + (g << 2)]);
            }
            cp_commit();
        }
    }

    // ---- epilogue: both Grams in registers, fuse kernels + classify ----
    const float ep    = g_par[0];
    const float invs  = g_par[1];
    const float invs0 = g_par[2];

    float rno[4], rnf[4], cno[8], cnf[8];
    #pragma unroll
    for (int mi = 0; mi < 2; mi++)
        #pragma unroll
        for (int rr = 0; rr < 2; rr++){
            int r = rowBase + rw + mi*16 + rr*8 + gid;
            rno[mi*2+rr] = g_onorm[r];
            rnf[mi*2+rr] = g_fnorm[r];
        }
    #pragma unroll
    for (int ni = 0; ni < 4; ni++)
        #pragma unroll
        for (int cc = 0; cc < 2; cc++){
            int ccol = colBase + cw + ni*8 + tig*2 + cc;
            cno[ni*2+cc] = g_onorm[ccol];
            cnf[ni*2+cc] = g_fnorm[ccol];
        }

    const float mult = (bi == bj) ? 1.f : 2.f;
    float sx = 0.f, sy = 0.f, smix = 0.f, sd = 0.f;
    #pragma unroll
    for (int mi = 0; mi < 2; mi++)
        #pragma unroll
        for (int rr = 0; rr < 2; rr++){
            const int ri = rowBase + rw + mi*16 + rr*8 + gid;
            const bool rX = ri < NHALF;
            #pragma unroll
            for (int ni = 0; ni < 4; ni++)
                #pragma unroll
                for (int cc = 0; cc < 2; cc++){
                    const int ci = colBase + cw + ni*8 + tig*2 + cc;
                    if (ri == ci) continue;          // diagonal excluded analytically
                    float d0 = fmaxf(rno[mi*2+rr] + cno[ni*2+cc]
                                     - 2.f * acc[mi][ni][rr*2+cc], 0.f);
                    float dd = fmaxf(rnf[mi*2+rr] + cnf[ni*2+cc]
                                     - 2.f * fac[mi][ni][rr*2+cc], 0.f);
                    float eo = exp_neg(d0 * invs);
                    float kv = (1.f - ep) * exp_neg(dd * invs0) * eo + ep * eo;
                    const bool cX = ci < NHALF;
                    if (rX && cX)        sx   += kv;
                    else if (!rX && !cX) sy   += kv;
                    else {
                        smix += kv;
                        if (ci - ri == NHALF || ri - ci == NHALF) sd += kv;
                    }
                }
        }
    sx *= mult; sy *= mult; smix *= mult;            // sd counted once per pair

    #pragma unroll
    for (int off = 16; off; off >>= 1){
        sx   += __shfl_xor_sync(0xffffffffu, sx,   off);
        sy   += __shfl_xor_sync(0xffffffffu, sy,   off);
        smix += __shfl_xor_sync(0xffffffffu, smix, off);
        sd   += __shfl_xor_sync(0xffffffffu, sd,   off);
    }
    if ((tid & 31) == 0){
        atomicAdd(&g_acc[0], (double)sx);
        atomicAdd(&g_acc[1], (double)sy);
        atomicAdd(&g_acc[2], (double)smix);
        atomicAdd(&g_acc[3], (double)sd);
    }
}

// ---------------- finalize ----------------
__global__ void fin_kernel(float* __restrict__ out){
    double n = (double)NHALF;
    double denom = n * (n - 1.0);
    double xx = g_acc[0] / denom;
    double yy = g_acc[1] / denom;
    double xy = (0.5 * g_acc[2] - g_acc[3]) / denom;
    out[0] = (float)(xx - 2.0 * xy + yy);
}

// ---------------- launch ----------------
extern "C" void kernel_launch(void* const* d_in, const int* in_sizes, int n_in,
                              void* d_out, int out_size){
    const float* Xs  = (const float*)d_in[0];
    const float* Xt  = (const float*)d_in[1];
    const float* W1  = (const float*)d_in[2];
    const float* b1  = (const float*)d_in[3];
    const float* W2  = (const float*)d_in[4];
    const float* b2  = (const float*)d_in[5];
    const float* W3  = (const float*)d_in[6];
    const float* b3  = (const float*)d_in[7];
    const float* W4  = (const float*)d_in[8];
    const float* b4  = (const float*)d_in[9];
    const float* eps = (const float*)d_in[10];
    const float* sg  = (const float*)d_in[11];
    const float* sg0 = (const float*)d_in[12];

    init_kernel<<<1, 32>>>(eps, sg, sg0);
    feat_kernel<<<NROWS/8, 256>>>(Xs, Xt, W1, b1, W2, b2, W3, b3, W4, b4);

    cudaFuncSetAttribute(pair_kernel, cudaFuncAttributeMaxDynamicSharedMemorySize, SMEM_BYTES);
    dim3 grid(NB, NB);
    pair_kernel<<<grid, NT, SMEM_BYTES>>>();

    fin_kernel<<<1, 1>>>((float*)d_out);
}

// round 7
// speedup vs baseline: 1.5551x; 1.5551x over previous
#include <cuda_runtime.h>
#include <cuda_bf16.h>
#include <math.h>
#include <stdint.h>

#define NROWS 8192
#define NHALF 4096
#define DIN   512
#define DF    64      // feature dim padded (50 -> 64, zeros)
#define DOUT  50
#define HID   10
#define BM    128
#define BN    128
#define BK    16      // phase-2 (fp32 SIMT) k-chunk
#define KC    64      // phase-1 k-chunk (bf16 elements; 128 B/row)
#define LDE   129     // padded lead dim for Et stage
#define NB    (NROWS/BM)   // 64
#define NCHUNK (DIN/KC)    // 8

// smem float offsets. bf16 tile = 128 rows x 64 bf16 = 16 KB = 4096 floats.
// Stage1 overlaps Et (Et written only after all MMAs done).
#define OFF_A0  0
#define OFF_B0  4096
#define OFF_A1  8192
#define OFF_B1  12288
#define OFF_ET  8192
#define SMEM_FLOATS (OFF_ET + BM*LDE)          // 24704
#define SMEM_BYTES  (SMEM_FLOATS * 4)          // 98,816 B -> 2 CTAs/SM

// -------- scratch (no dynamic allocation allowed) --------
__device__ __nv_bfloat16 g_XcatH[NROWS*DIN];  // bf16-rounded concat(Xs,Xt), 8 MB
__device__ float  g_Fea [NROWS*DF];      // padded features (fp32)
__device__ float  g_onorm[NROWS];        // norms of bf16-ROUNDED originals
__device__ float  g_fnorm[NROWS];
__device__ double g_acc[4];              // Sx, Sy, Smixed(2*sumKxy), Sdiag_xy
__device__ float  g_par[3];              // ep, 1/sigma, 1/sigma0

__device__ __forceinline__ float softplus_f(float x){
    return fmaxf(x, 0.f) + log1pf(expf(-fabsf(x)));
}

// exp(-x) for x >= 0, FMA-pipe only (no MUFU). ~3e-7 relative error.
__device__ __forceinline__ float exp_neg(float x){
    float t = x * -1.4426950408889634f;
    t = fmaxf(t, -125.f);
    float fn = t + 12582912.f;                   // 2^23 + 2^22 round magic
    int   ni = __float_as_int(fn) - 0x4B400000;
    float r  = t - (fn - 12582912.f);
    float p  = 1.5403530393e-4f;
    p = fmaf(p, r, 1.3333558146e-3f);
    p = fmaf(p, r, 9.6181291076e-3f);
    p = fmaf(p, r, 5.5504108665e-2f);
    p = fmaf(p, r, 2.4022650696e-1f);
    p = fmaf(p, r, 6.9314718056e-1f);
    p = fmaf(p, r, 1.0f);
    return __int_as_float(__float_as_int(p) + (ni << 23));
}

__device__ __forceinline__ void cp16(float* dst, const void* src){
    uint32_t d = (uint32_t)__cvta_generic_to_shared(dst);
    asm volatile("cp.async.cg.shared.global [%0], [%1], 16;\n"
                 :: "r"(d), "l"(src) : "memory");
}
__device__ __forceinline__ void cp_commit(){
    asm volatile("cp.async.commit_group;\n" ::: "memory");
}

// ---------------- init ----------------
__global__ void init_kernel(const float* __restrict__ eps,
                            const float* __restrict__ sig,
                            const float* __restrict__ sig0){
    if (threadIdx.x == 0){
        g_par[0] = 1.f / (1.f + expf(-eps[0]));
        g_par[1] = 1.f / (sig[0]  * sig[0]);
        g_par[2] = 1.f / (sig0[0] * sig0[0]);
        g_acc[0] = 0.0; g_acc[1] = 0.0; g_acc[2] = 0.0; g_acc[3] = 0.0;
    }
}

// ---------------- featurize: warp per row ----------------
__global__ __launch_bounds__(256)
void feat_kernel(const float* __restrict__ Xs, const float* __restrict__ Xt,
                 const float* __restrict__ W1, const float* __restrict__ b1,
                 const float* __restrict__ W2, const float* __restrict__ b2,
                 const float* __restrict__ W3, const float* __restrict__ b3,
                 const float* __restrict__ W4, const float* __restrict__ b4)
{
    __shared__ float sW1[DIN*HID];
    __shared__ float sW2[HID*HID], sW3[HID*HID], sW4[HID*DOUT];
    __shared__ float sb1[HID], sb2[HID], sb3[HID], sb4[DOUT];
    int tid = threadIdx.x;
    for (int i = tid; i < DIN*HID; i += 256) sW1[i] = W1[i];
    for (int i = tid; i < HID*HID; i += 256){ sW2[i] = W2[i]; sW3[i] = W3[i]; }
    for (int i = tid; i < HID*DOUT; i += 256) sW4[i] = W4[i];
    if (tid < HID){ sb1[tid] = b1[tid]; sb2[tid] = b2[tid]; sb3[tid] = b3[tid]; }
    if (tid < DOUT) sb4[tid] = b4[tid];
    __syncthreads();

    int warp = tid >> 5, lane = tid & 31;
    int row = blockIdx.x * 8 + warp;
    if (row >= NROWS) return;
    const float* src = (row < NHALF) ? (Xs + (size_t)row * DIN)
                                     : (Xt + (size_t)(row - NHALF) * DIN);
    float acc[HID];
    #pragma unroll
    for (int o = 0; o < HID; o++) acc[o] = 0.f;
    float on = 0.f;
    for (int k = lane; k < DIN; k += 32){
        float x = src[k];
        // bf16-round (rn) ONCE; Gram and norms use the rounded value consistently,
        // so Do is the EXACT distance between the perturbed inputs (no accum bias).
        __nv_bfloat16 xb = __float2bfloat16_rn(x);
        float xf = __bfloat162float(xb);
        g_XcatH[(size_t)row * DIN + k] = xb;
        on += xf * xf;
        #pragma unroll
        for (int o = 0; o < HID; o++) acc[o] += x * sW1[k*HID + o];
    }
    #pragma unroll
    for (int off = 16; off; off >>= 1){
        on += __shfl_xor_sync(0xffffffffu, on, off);
        #pragma unroll
        for (int o = 0; o < HID; o++)
            acc[o] += __shfl_xor_sync(0xffffffffu, acc[o], off);
    }
    if (lane == 0) g_onorm[row] = on;

    float h1[HID], h2[HID], h3[HID];
    #pragma unroll
    for (int o = 0; o < HID; o++) h1[o] = softplus_f(acc[o] + sb1[o]);
    #pragma unroll
    for (int o = 0; o < HID; o++){
        float t = sb2[o];
        #pragma unroll
        for (int p = 0; p < HID; p++) t += h1[p] * sW2[p*HID + o];
        h2[o] = softplus_f(t);
    }
    #pragma unroll
    for (int o = 0; o < HID; o++){
        float t = sb3[o];
        #pragma unroll
        for (int p = 0; p < HID; p++) t += h2[p] * sW3[p*HID + o];
        h3[o] = softplus_f(t);
    }
    float fn = 0.f;
    for (int c = lane; c < DF; c += 32){
        float v = 0.f;
        if (c < DOUT){
            v = sb4[c];
            #pragma unroll
            for (int p = 0; p < HID; p++) v += h3[p] * sW4[p*DOUT + c];
        }
        g_Fea[(size_t)row * DF + c] = v;
        fn += v * v;
    }
    #pragma unroll
    for (int off = 16; off; off >>= 1)
        fn += __shfl_xor_sync(0xffffffffu, fn, off);
    if (lane == 0) g_fnorm[row] = fn;
}

// ---------------- fused pairwise kernel ----------------
__global__ __launch_bounds__(256, 2)
void pair_kernel(){
    int bj = blockIdx.x, bi = blockIdx.y;
    if (bj < bi) return;                       // upper-triangle tiles only
    extern __shared__ float smem[];

    const int tid  = threadIdx.x;
    const int lane = tid & 31, warp = tid >> 5;
    const int gid  = lane >> 2, tig = lane & 3;
    const int warpM = warp >> 1, warpN = warp & 1;   // 4 x 2 warp grid
    const int rw = warpM * 32;                 // warp row base (local)
    const int cw = warpN * 64;                 // warp col base (local)
    const int rowBase = bi * BM, colBase = bj * BN;

    // ---- phase 1: original-space Gram via bf16 m16n8k16 (K = 512) ----
    // Tiles: 128 rows x 64 bf16 (128 B/row), SW128-style swizzle g' = g ^ (row&7).
    float acc[2][8][4];
    #pragma unroll
    for (int mi = 0; mi < 2; mi++)
        #pragma unroll
        for (int ni = 0; ni < 8; ni++)
            #pragma unroll
            for (int r = 0; r < 4; r++) acc[mi][ni][r] = 0.f;

    // prefetch chunks 0 and 1
    #pragma unroll
    for (int st = 0; st < 2; st++){
        float* bA = smem + (st ? OFF_A1 : OFF_A0);
        float* bB = smem + (st ? OFF_B1 : OFF_B0);
        int kb = st * KC;
        #pragma unroll
        for (int i = 0; i < 4; i++){
            int idx = tid + i * 256;           // 1024 16B-granules per tile
            int r = idx >> 3, g = idx & 7;     // row 0..127, granule 0..7 (8 bf16)
            int sw = r*32 + (((g ^ (r & 7)) << 2));
            cp16(bA + sw, &g_XcatH[(size_t)(rowBase + r)*DIN + kb + (g << 3)]);
            cp16(bB + sw, &g_XcatH[(size_t)(colBase + r)*DIN + kb + (g << 3)]);
        }
        cp_commit();
    }

    for (int c = 0; c < NCHUNK; c++){
        if (c < NCHUNK - 1) asm volatile("cp.async.wait_group 1;\n" ::: "memory");
        else                asm volatile("cp.async.wait_group 0;\n" ::: "memory");
        __syncthreads();

        const float* Ash = smem + ((c & 1) ? OFF_A1 : OFF_A0);
        const float* Bsh = smem + ((c & 1) ? OFF_B1 : OFF_B0);

        #pragma unroll
        for (int ks = 0; ks < 4; ks++){        // 4 k16-steps per 64-elem chunk
            const int g0 = 2*ks, g1 = 2*ks + 1;
            uint32_t bfr[8][2];
            #pragma unroll
            for (int ni = 0; ni < 8; ni++){
                int row = cw + ni*8 + gid;
                int rb = row * 32;
                int m7 = row & 7;
                bfr[ni][0] = __float_as_uint(Bsh[rb + ((g0 ^ m7) << 2) + tig]);
                bfr[ni][1] = __float_as_uint(Bsh[rb + ((g1 ^ m7) << 2) + tig]);
            }
            #pragma unroll
            for (int mi = 0; mi < 2; mi++){
                int row0 = rw + mi*16 + gid, row1 = row0 + 8;
                int r0 = row0 * 32, r1 = row1 * 32;
                int m70 = row0 & 7, m71 = row1 & 7;
                uint32_t a0 = __float_as_uint(Ash[r0 + ((g0 ^ m70) << 2) + tig]);
                uint32_t a1 = __float_as_uint(Ash[r1 + ((g0 ^ m71) << 2) + tig]);
                uint32_t a2 = __float_as_uint(Ash[r0 + ((g1 ^ m70) << 2) + tig]);
                uint32_t a3 = __float_as_uint(Ash[r1 + ((g1 ^ m71) << 2) + tig]);
                #pragma unroll
                for (int ni = 0; ni < 8; ni++){
                    asm volatile(
                        "mma.sync.aligned.m16n8k16.row.col.f32.bf16.bf16.f32 "
                        "{%0,%1,%2,%3}, {%4,%5,%6,%7}, {%8,%9}, {%0,%1,%2,%3};\n"
                        : "+f"(acc[mi][ni][0]), "+f"(acc[mi][ni][1]),
                          "+f"(acc[mi][ni][2]), "+f"(acc[mi][ni][3])
                        : "r"(a0), "r"(a1), "r"(a2), "r"(a3),
                          "r"(bfr[ni][0]), "r"(bfr[ni][1]));
                }
            }
        }
        __syncthreads();     // all warps done reading buf[c&1] before refill

        if (c + 2 < NCHUNK){
            float* bA = smem + ((c & 1) ? OFF_A1 : OFF_A0);
            float* bB = smem + ((c & 1) ? OFF_B1 : OFF_B0);
            int kb = (c + 2) * KC;
            #pragma unroll
            for (int i = 0; i < 4; i++){
                int idx = tid + i * 256;
                int r = idx >> 3, g = idx & 7;
                int sw = r*32 + (((g ^ (r & 7)) << 2));
                cp16(bA + sw, &g_XcatH[(size_t)(rowBase + r)*DIN + kb + (g << 3)]);
                cp16(bB + sw, &g_XcatH[(size_t)(colBase + r)*DIN + kb + (g << 3)]);
            }
            cp_commit();
        }
    }

    const float ep    = g_par[0];
    const float invs  = g_par[1];
    const float invs0 = g_par[2];
    float* Et = smem + OFF_ET;                 // [128][LDE]

    {   // convert Do -> e_org, stage into Et (frag layout -> (row, col))
        float rn[4], cn[16];
        #pragma unroll
        for (int mi = 0; mi < 2; mi++)
            #pragma unroll
            for (int rr = 0; rr < 2; rr++)
                rn[mi*2+rr] = g_onorm[rowBase + rw + mi*16 + rr*8 + gid];
        #pragma unroll
        for (int ni = 0; ni < 8; ni++)
            #pragma unroll
            for (int cc = 0; cc < 2; cc++)
                cn[ni*2+cc] = g_onorm[colBase + cw + ni*8 + tig*2 + cc];
        #pragma unroll
        for (int mi = 0; mi < 2; mi++)
            #pragma unroll
            for (int ni = 0; ni < 8; ni++)
                #pragma unroll
                for (int rr = 0; rr < 2; rr++)
                    #pragma unroll
                    for (int cc = 0; cc < 2; cc++){
                        int lm = rw + mi*16 + rr*8 + gid;
                        int ln = cw + ni*8 + tig*2 + cc;
                        float d = fmaxf(rn[mi*2+rr] + cn[ni*2+cc]
                                        - 2.f * acc[mi][ni][rr*2+cc], 0.f);
                        Et[lm*LDE + ln] = exp_neg(d * invs);
                    }
    }
    __syncthreads();

    // ---- phase 2: feature-space Gram, fp32 SIMT (K = 64 padded) ----
    float* As2 = smem;                 // [BK][BM] transposed tile
    float* Bs2 = smem + BK*BM;         // [BK][BN]
    const int tx = tid & 15, ty = tid >> 4;
    const int lr = tid >> 2;           // 0..63
    const int lc = (tid & 3) << 2;     // 0,4,8,12

    float fac[8][8];
    #pragma unroll
    for (int m = 0; m < 8; m++)
        #pragma unroll
        for (int n = 0; n < 8; n++) fac[m][n] = 0.f;

    for (int kb = 0; kb < DF; kb += BK){
        float4 a0 = *(const float4*)&g_Fea[(size_t)(rowBase+lr   )*DF + kb + lc];
        float4 a1 = *(const float4*)&g_Fea[(size_t)(rowBase+lr+64)*DF + kb + lc];
        float4 b0 = *(const float4*)&g_Fea[(size_t)(colBase+lr   )*DF + kb + lc];
        float4 b1 = *(const float4*)&g_Fea[(size_t)(colBase+lr+64)*DF + kb + lc];
        As2[(lc+0)*BM + lr] = a0.x; As2[(lc+1)*BM + lr] = a0.y;
        As2[(lc+2)*BM + lr] = a0.z; As2[(lc+3)*BM + lr] = a0.w;
        As2[(lc+0)*BM + lr+64] = a1.x; As2[(lc+1)*BM + lr+64] = a1.y;
        As2[(lc+2)*BM + lr+64] = a1.z; As2[(lc+3)*BM + lr+64] = a1.w;
        Bs2[(lc+0)*BN + lr] = b0.x; Bs2[(lc+1)*BN + lr] = b0.y;
        Bs2[(lc+2)*BN + lr] = b0.z; Bs2[(lc+3)*BN + lr] = b0.w;
        Bs2[(lc+0)*BN + lr+64] = b1.x; Bs2[(lc+1)*BN + lr+64] = b1.y;
        Bs2[(lc+2)*BN + lr+64] = b1.z; Bs2[(lc+3)*BN + lr+64] = b1.w;
        __syncthreads();
        #pragma unroll
        for (int k = 0; k < BK; k++){
            float a[8], b[8];
            #pragma unroll
            for (int m = 0; m < 8; m++) a[m] = As2[k*BM + ty*8 + m];
            #pragma unroll
            for (int n = 0; n < 8; n++) b[n] = Bs2[k*BN + tx*8 + n];
            #pragma unroll
            for (int m = 0; m < 8; m++)
                #pragma unroll
                for (int n = 0; n < 8; n++) fac[m][n] += a[m] * b[n];
        }
        __syncthreads();
    }

    // ---- final epilogue: deep kernel + classified reduction ----
    float fnr[8], fnc[8];
    #pragma unroll
    for (int m = 0; m < 8; m++) fnr[m] = g_fnorm[rowBase + ty*8 + m];
    #pragma unroll
    for (int n = 0; n < 8; n++) fnc[n] = g_fnorm[colBase + tx*8 + n];

    const float mult = (bi == bj) ? 1.f : 2.f;
    float sx = 0.f, sy = 0.f, smix = 0.f, sd = 0.f;
    #pragma unroll
    for (int m = 0; m < 8; m++){
        const int ri = rowBase + ty*8 + m;
        const bool rX = ri < NHALF;
        #pragma unroll
        for (int n = 0; n < 8; n++){
            const int ci = colBase + tx*8 + n;
            if (ri == ci) continue;                      // diagonal excluded analytically
            float dd = fmaxf(fnr[m] + fnc[n] - 2.f * fac[m][n], 0.f);
            float eo = Et[(ty*8+m)*LDE + tx*8 + n];
            float kv = (1.f - ep) * exp_neg(dd * invs0) * eo + ep * eo;
            const bool cX = ci < NHALF;
            if (rX && cX)        sx   += kv;
            else if (!rX && !cX) sy   += kv;
            else {
                smix += kv;
                if (ci - ri == NHALF || ri - ci == NHALF) sd += kv;
            }
        }
    }
    sx *= mult; sy *= mult; smix *= mult;                // sd counted once per pair

    #pragma unroll
    for (int off = 16; off; off >>= 1){
        sx   += __shfl_xor_sync(0xffffffffu, sx,   off);
        sy   += __shfl_xor_sync(0xffffffffu, sy,   off);
        smix += __shfl_xor_sync(0xffffffffu, smix, off);
        sd   += __shfl_xor_sync(0xffffffffu, sd,   off);
    }
    if ((tid & 31) == 0){
        atomicAdd(&g_acc[0], (double)sx);
        atomicAdd(&g_acc[1], (double)sy);
        atomicAdd(&g_acc[2], (double)smix);
        atomicAdd(&g_acc[3], (double)sd);
    }
}

// ---------------- finalize ----------------
__global__ void fin_kernel(float* __restrict__ out){
    double n = (double)NHALF;
    double denom = n * (n - 1.0);
    double xx = g_acc[0] / denom;
    double yy = g_acc[1] / denom;
    double xy = (0.5 * g_acc[2] - g_acc[3]) / denom;
    out[0] = (float)(xx - 2.0 * xy + yy);
}

// ---------------- launch ----------------
extern "C" void kernel_launch(void* const* d_in, const int* in_sizes, int n_in,
                              void* d_out, int out_size){
    const float* Xs  = (const float*)d_in[0];
    const float* Xt  = (const float*)d_in[1];
    const float* W1  = (const float*)d_in[2];
    const float* b1  = (const float*)d_in[3];
    const float* W2  = (const float*)d_in[4];
    const float* b2  = (const float*)d_in[5];
    const float* W3  = (const float*)d_in[6];
    const float* b3  = (const float*)d_in[7];
    const float* W4  = (const float*)d_in[8];
    const float* b4  = (const float*)d_in[9];
    const float* eps = (const float*)d_in[10];
    const float* sg  = (const float*)d_in[11];
    const float* sg0 = (const float*)d_in[12];

    init_kernel<<<1, 32>>>(eps, sg, sg0);
    feat_kernel<<<NROWS/8, 256>>>(Xs, Xt, W1, b1, W2, b2, W3, b3, W4, b4);

    cudaFuncSetAttribute(pair_kernel, cudaFuncAttributeMaxDynamicSharedMemorySize, SMEM_BYTES);
    dim3 grid(NB, NB);
    pair_kernel<<<grid, 256, SMEM_BYTES>>>();

    fin_kernel<<<1, 1>>>((float*)d_out);
}

// round 10
// speedup vs baseline: 1.7194x; 1.1056x over previous
#include <cuda_runtime.h>
#include <cuda_bf16.h>
#include <cuda_fp16.h>
#include <math.h>
#include <stdint.h>

#define NROWS 8192
#define NHALF 4096
#define DIN   512
#define DF    64      // feature dim padded (50 -> 64, zeros)
#define DOUT  50
#define HID   10
#define BM    128
#define BN    128
#define KC    64      // phase-1 k-chunk (bf16 elements; 128 B/row)
#define NB    (NROWS/BM)   // 64
#define NCHUNK (DIN/KC)    // 8
#define LDEH  130     // Et fp16 lead dim (halves)

// smem float offsets. Phase-1 bf16 tiles: A0,B0,A1,B1 (4096 floats each).
// Phase-2 transposed Fea tiles: FA_t = [0,8192), FB_t = [8192,16384)
// (reuse phase-1 buffers after their final consumption sync).
// Et fp16 at float offset 16384 (no overlap with anything live).
#define OFF_A0  0
#define OFF_B0  4096
#define OFF_A1  8192
#define OFF_B1  12288
#define OFF_ET16 16384                         // as halves: byte 65536
#define SMEM_FLOATS (OFF_ET16 + (BM*LDEH)/2)   // 16384 + 8320 = 24704
#define SMEM_BYTES  (SMEM_FLOATS * 4)          // 98,816 B -> 2 CTAs/SM

// -------- scratch (no dynamic allocation allowed) --------
__device__ __nv_bfloat16 g_XcatH[NROWS*DIN];  // bf16-rounded concat(Xs,Xt), 8 MB
__device__ float  g_FeaT[DF*NROWS];      // TRANSPOSED features [k][row], fp32
__device__ float  g_onorm[NROWS];        // norms of bf16-ROUNDED originals
__device__ float  g_fnorm[NROWS];
__device__ double g_acc[4];              // Sx, Sy, Smixed(2*sumKxy), Sdiag_xy
__device__ float  g_par[3];              // ep, 1/sigma, 1/sigma0

__device__ __forceinline__ float softplus_f(float x){
    return fmaxf(x, 0.f) + log1pf(expf(-fabsf(x)));
}

// exp(-x) for x >= 0, FMA-pipe only (no MUFU). ~3e-7 relative error.
__device__ __forceinline__ float exp_neg(float x){
    float t = x * -1.4426950408889634f;
    t = fmaxf(t, -125.f);
    float fn = t + 12582912.f;                   // 2^23 + 2^22 round magic
    int   ni = __float_as_int(fn) - 0x4B400000;
    float r  = t - (fn - 12582912.f);
    float p  = 1.5403530393e-4f;
    p = fmaf(p, r, 1.3333558146e-3f);
    p = fmaf(p, r, 9.6181291076e-3f);
    p = fmaf(p, r, 5.5504108665e-2f);
    p = fmaf(p, r, 2.4022650696e-1f);
    p = fmaf(p, r, 6.9314718056e-1f);
    p = fmaf(p, r, 1.0f);
    return __int_as_float(__float_as_int(p) + (ni << 23));
}

__device__ __forceinline__ void cp16(float* dst, const void* src){
    uint32_t d = (uint32_t)__cvta_generic_to_shared(dst);
    asm volatile("cp.async.cg.shared.global [%0], [%1], 16;\n"
                 :: "r"(d), "l"(src) : "memory");
}
__device__ __forceinline__ void cp_commit(){
    asm volatile("cp.async.commit_group;\n" ::: "memory");
}

// ---------------- init ----------------
__global__ void init_kernel(const float* __restrict__ eps,
                            const float* __restrict__ sig,
                            const float* __restrict__ sig0){
    if (threadIdx.x == 0){
        g_par[0] = 1.f / (1.f + expf(-eps[0]));
        g_par[1] = 1.f / (sig[0]  * sig[0]);
        g_par[2] = 1.f / (sig0[0] * sig0[0]);
        g_acc[0] = 0.0; g_acc[1] = 0.0; g_acc[2] = 0.0; g_acc[3] = 0.0;
    }
}

// ---------------- featurize: warp per row ----------------
__global__ __launch_bounds__(256)
void feat_kernel(const float* __restrict__ Xs, const float* __restrict__ Xt,
                 const float* __restrict__ W1, const float* __restrict__ b1,
                 const float* __restrict__ W2, const float* __restrict__ b2,
                 const float* __restrict__ W3, const float* __restrict__ b3,
                 const float* __restrict__ W4, const float* __restrict__ b4)
{
    __shared__ float sW1[DIN*HID];
    __shared__ float sW2[HID*HID], sW3[HID*HID], sW4[HID*DOUT];
    __shared__ float sb1[HID], sb2[HID], sb3[HID], sb4[DOUT];
    int tid = threadIdx.x;
    for (int i = tid; i < DIN*HID; i += 256) sW1[i] = W1[i];
    for (int i = tid; i < HID*HID; i += 256){ sW2[i] = W2[i]; sW3[i] = W3[i]; }
    for (int i = tid; i < HID*DOUT; i += 256) sW4[i] = W4[i];
    if (tid < HID){ sb1[tid] = b1[tid]; sb2[tid] = b2[tid]; sb3[tid] = b3[tid]; }
    if (tid < DOUT) sb4[tid] = b4[tid];
    __syncthreads();

    int warp = tid >> 5, lane = tid & 31;
    int row = blockIdx.x * 8 + warp;
    if (row >= NROWS) return;
    const float* src = (row < NHALF) ? (Xs + (size_t)row * DIN)
                                     : (Xt + (size_t)(row - NHALF) * DIN);
    float acc[HID];
    #pragma unroll
    for (int o = 0; o < HID; o++) acc[o] = 0.f;
    float on = 0.f;
    for (int k = lane; k < DIN; k += 32){
        float x = src[k];
        // bf16-round (rn) ONCE; Gram and norms use the rounded value consistently,
        // so Do is the EXACT distance between the perturbed inputs (no accum bias).
        __nv_bfloat16 xb = __float2bfloat16_rn(x);
        float xf = __bfloat162float(xb);
        g_XcatH[(size_t)row * DIN + k] = xb;
        on += xf * xf;
        #pragma unroll
        for (int o = 0; o < HID; o++) acc[o] += x * sW1[k*HID + o];
    }
    #pragma unroll
    for (int off = 16; off; off >>= 1){
        on += __shfl_xor_sync(0xffffffffu, on, off);
        #pragma unroll
        for (int o = 0; o < HID; o++)
            acc[o] += __shfl_xor_sync(0xffffffffu, acc[o], off);
    }
    if (lane == 0) g_onorm[row] = on;

    float h1[HID], h2[HID], h3[HID];
    #pragma unroll
    for (int o = 0; o < HID; o++) h1[o] = softplus_f(acc[o] + sb1[o]);
    #pragma unroll
    for (int o = 0; o < HID; o++){
        float t = sb2[o];
        #pragma unroll
        for (int p = 0; p < HID; p++) t += h1[p] * sW2[p*HID + o];
        h2[o] = softplus_f(t);
    }
    #pragma unroll
    for (int o = 0; o < HID; o++){
        float t = sb3[o];
        #pragma unroll
        for (int p = 0; p < HID; p++) t += h2[p] * sW3[p*HID + o];
        h3[o] = softplus_f(t);
    }
    // Write features TRANSPOSED: g_FeaT[k][row] (phase-2 tiles cp.async directly).
    float fn = 0.f;
    for (int c = lane; c < DF; c += 32){
        float v = 0.f;
        if (c < DOUT){
            v = sb4[c];
            #pragma unroll
            for (int p = 0; p < HID; p++) v += h3[p] * sW4[p*DOUT + c];
        }
        g_FeaT[(size_t)c * NROWS + row] = v;
        fn += v * v;
    }
    #pragma unroll
    for (int off = 16; off; off >>= 1)
        fn += __shfl_xor_sync(0xffffffffu, fn, off);
    if (lane == 0) g_fnorm[row] = fn;
}

// ---------------- fused pairwise kernel ----------------
__global__ __launch_bounds__(256, 2)
void pair_kernel(){
    int bj = blockIdx.x, bi = blockIdx.y;
    if (bj < bi) return;                       // upper-triangle tiles only
    extern __shared__ float smem[];

    const int tid  = threadIdx.x;
    const int lane = tid & 31, warp = tid >> 5;
    const int gid  = lane >> 2, tig = lane & 3;
    const int warpM = warp >> 1, warpN = warp & 1;   // 4 x 2 warp grid
    const int rw = warpM * 32;                 // warp row base (local)
    const int cw = warpN * 64;                 // warp col base (local)
    const int rowBase = bi * BM, colBase = bj * BN;

    // ---- phase 1: original-space Gram via bf16 m16n8k16 (K = 512) ----
    float acc[2][8][4];
    #pragma unroll
    for (int mi = 0; mi < 2; mi++)
        #pragma unroll
        for (int ni = 0; ni < 8; ni++)
            #pragma unroll
            for (int r = 0; r < 4; r++) acc[mi][ni][r] = 0.f;

    // prefetch chunks 0 and 1 (row = 128 B; granule swizzle g' = g ^ (row&7))
    #pragma unroll
    for (int st = 0; st < 2; st++){
        float* bA = smem + (st ? OFF_A1 : OFF_A0);
        float* bB = smem + (st ? OFF_B1 : OFF_B0);
        int kb = st * KC;
        #pragma unroll
        for (int i = 0; i < 4; i++){
            int idx = tid + i * 256;           // 1024 16B-granules per tile
            int r = idx >> 3, g = idx & 7;
            int sw = r*32 + (((g ^ (r & 7)) << 2));
            cp16(bA + sw, &g_XcatH[(size_t)(rowBase + r)*DIN + kb + (g << 3)]);
            cp16(bB + sw, &g_XcatH[(size_t)(colBase + r)*DIN + kb + (g << 3)]);
        }
        cp_commit();
    }

    for (int c = 0; c < NCHUNK; c++){
        if (c < NCHUNK - 1) asm volatile("cp.async.wait_group 1;\n" ::: "memory");
        else                asm volatile("cp.async.wait_group 0;\n" ::: "memory");
        __syncthreads();

        const float* Ash = smem + ((c & 1) ? OFF_A1 : OFF_A0);
        const float* Bsh = smem + ((c & 1) ? OFF_B1 : OFF_B0);

        #pragma unroll
        for (int ks = 0; ks < 4; ks++){        // 4 k16-steps per 64-elem chunk
            const int g0 = 2*ks, g1 = 2*ks + 1;
            uint32_t bfr[8][2];
            #pragma unroll
            for (int ni = 0; ni < 8; ni++){
                int rb = (cw + ni*8 + gid) * 32;   // row&7 == gid
                bfr[ni][0] = __float_as_uint(Bsh[rb + ((g0 ^ gid) << 2) + tig]);
                bfr[ni][1] = __float_as_uint(Bsh[rb + ((g1 ^ gid) << 2) + tig]);
            }
            #pragma unroll
            for (int mi = 0; mi < 2; mi++){
                int r0 = (rw + mi*16 + gid) * 32, r1 = r0 + 8*32;
                uint32_t a0 = __float_as_uint(Ash[r0 + ((g0 ^ gid) << 2) + tig]);
                uint32_t a1 = __float_as_uint(Ash[r1 + ((g0 ^ gid) << 2) + tig]);
                uint32_t a2 = __float_as_uint(Ash[r0 + ((g1 ^ gid) << 2) + tig]);
                uint32_t a3 = __float_as_uint(Ash[r1 + ((g1 ^ gid) << 2) + tig]);
                #pragma unroll
                for (int ni = 0; ni < 8; ni++){
                    asm volatile(
                        "mma.sync.aligned.m16n8k16.row.col.f32.bf16.bf16.f32 "
                        "{%0,%1,%2,%3}, {%4,%5,%6,%7}, {%8,%9}, {%0,%1,%2,%3};\n"
                        : "+f"(acc[mi][ni][0]), "+f"(acc[mi][ni][1]),
                          "+f"(acc[mi][ni][2]), "+f"(acc[mi][ni][3])
                        : "r"(a0), "r"(a1), "r"(a2), "r"(a3),
                          "r"(bfr[ni][0]), "r"(bfr[ni][1]));
                }
            }
        }
        __syncthreads();     // all warps done reading buf[c&1] before refill

        if (c + 2 < NCHUNK){
            float* bA = smem + ((c & 1) ? OFF_A1 : OFF_A0);
            float* bB = smem + ((c & 1) ? OFF_B1 : OFF_B0);
            int kb = (c + 2) * KC;
            #pragma unroll
            for (int i = 0; i < 4; i++){
                int idx = tid + i * 256;
                int r = idx >> 3, g = idx & 7;
                int sw = r*32 + (((g ^ (r & 7)) << 2));
                cp16(bA + sw, &g_XcatH[(size_t)(rowBase + r)*DIN + kb + (g << 3)]);
                cp16(bB + sw, &g_XcatH[(size_t)(colBase + r)*DIN + kb + (g << 3)]);
            }
            cp_commit();
        }
    }
    // All phase-1 buffers dead now (end-of-loop sync above).

    // Prefetch BOTH transposed Fea tiles (fp32) into [0,16384) floats,
    // overlapped with the Et epilogue below.
    // FA_t[k][128] <- g_FeaT[k][rowBase..+127]; FB_t at +8192 <- colBase.
    #pragma unroll
    for (int i = 0; i < 8; i++){
        int idx = tid + i * 256;               // 2048 granules each tile
        int k = idx >> 5, gr = (idx & 31) << 2;
        cp16(smem + k*128 + gr,        &g_FeaT[(size_t)k*NROWS + rowBase + gr]);
        cp16(smem + 8192 + k*128 + gr, &g_FeaT[(size_t)k*NROWS + colBase + gr]);
    }
    cp_commit();

    const float ep    = g_par[0];
    const float invs  = g_par[1];
    const float invs0 = g_par[2];
    __half* Et16 = (__half*)(smem + OFF_ET16); // [128][LDEH] halves

    {   // phase-1 epilogue: Do -> e_org, stage into Et16 (fragment -> (row,col))
        float rn[4], cn[16];
        #pragma unroll
        for (int mi = 0; mi < 2; mi++)
            #pragma unroll
            for (int rr = 0; rr < 2; rr++)
                rn[mi*2+rr] = g_onorm[rowBase + rw + mi*16 + rr*8 + gid];
        #pragma unroll
        for (int ni = 0; ni < 8; ni++)
            #pragma unroll
            for (int cc = 0; cc < 2; cc++)
                cn[ni*2+cc] = g_onorm[colBase + cw + ni*8 + tig*2 + cc];
        #pragma unroll
        for (int mi = 0; mi < 2; mi++)
            #pragma unroll
            for (int ni = 0; ni < 8; ni++)
                #pragma unroll
                for (int rr = 0; rr < 2; rr++)
                    #pragma unroll
                    for (int cc = 0; cc < 2; cc++){
                        int lm = rw + mi*16 + rr*8 + gid;
                        int ln = cw + ni*8 + tig*2 + cc;
                        float d = fmaxf(rn[mi*2+rr] + cn[ni*2+cc]
                                        - 2.f * acc[mi][ni][rr*2+cc], 0.f);
                        Et16[lm*LDEH + ln] = __float2half(exp_neg(d * invs));
                    }
    }

    asm volatile("cp.async.wait_group 0;\n" ::: "memory");
    __syncthreads();                           // Fea tiles + Et16 visible

    // ---- phase 2: feature Gram, fp32 SIMT (RN accumulate — bias-free),
    //      one-shot tiles, zero additional loads/syncs ----
    const float* FAt = smem;                   // [64][128]
    const float* FBt = smem + 8192;            // [64][128]
    const int tx = tid & 15, ty = tid >> 4;

    float fac[8][8];
    #pragma unroll
    for (int m = 0; m < 8; m++)
        #pragma unroll
        for (int n = 0; n < 8; n++) fac[m][n] = 0.f;

    for (int kb = 0; kb < DF; kb += 16){
        #pragma unroll
        for (int k16 = 0; k16 < 16; k16++){
            const int k = kb + k16;
            float a[8], b[8];
            #pragma unroll
            for (int m = 0; m < 8; m++) a[m] = FAt[k*128 + ty*8 + m];
            #pragma unroll
            for (int n = 0; n < 8; n++) b[n] = FBt[k*128 + tx*8 + n];
            #pragma unroll
            for (int m = 0; m < 8; m++)
                #pragma unroll
                for (int n = 0; n < 8; n++) fac[m][n] += a[m] * b[n];
        }
    }

    // ---- final epilogue: deep kernel + classified reduction (SIMT layout) ----
    float fnr[8], fnc[8];
    #pragma unroll
    for (int m = 0; m < 8; m++) fnr[m] = g_fnorm[rowBase + ty*8 + m];
    #pragma unroll
    for (int n = 0; n < 8; n++) fnc[n] = g_fnorm[colBase + tx*8 + n];

    const float mult = (bi == bj) ? 1.f : 2.f;
    float sx = 0.f, sy = 0.f, smix = 0.f, sd = 0.f;
    #pragma unroll
    for (int m = 0; m < 8; m++){
        const int ri = rowBase + ty*8 + m;
        const bool rX = ri < NHALF;
        #pragma unroll
        for (int n = 0; n < 8; n++){
            const int ci = colBase + tx*8 + n;
            if (ri == ci) continue;                      // diagonal excluded analytically
            float dd = fmaxf(fnr[m] + fnc[n] - 2.f * fac[m][n], 0.f);
            float eo = __half2float(Et16[(ty*8+m)*LDEH + tx*8 + n]);
            float kv = (1.f - ep) * exp_neg(dd * invs0) * eo + ep * eo;
            const bool cX = ci < NHALF;
            if (rX && cX)        sx   += kv;
            else if (!rX && !cX) sy   += kv;
            else {
                smix += kv;
                if (ci - ri == NHALF || ri - ci == NHALF) sd += kv;
            }
        }
    }
    sx *= mult; sy *= mult; smix *= mult;                // sd counted once per pair

    #pragma unroll
    for (int off = 16; off; off >>= 1){
        sx   += __shfl_xor_sync(0xffffffffu, sx,   off);
        sy   += __shfl_xor_sync(0xffffffffu, sy,   off);
        smix += __shfl_xor_sync(0xffffffffu, smix, off);
        sd   += __shfl_xor_sync(0xffffffffu, sd,   off);
    }
    if ((tid & 31) == 0){
        atomicAdd(&g_acc[0], (double)sx);
        atomicAdd(&g_acc[1], (double)sy);
        atomicAdd(&g_acc[2], (double)smix);
        atomicAdd(&g_acc[3], (double)sd);
    }
}

// ---------------- finalize ----------------
__global__ void fin_kernel(float* __restrict__ out){
    double n = (double)NHALF;
    double denom = n * (n - 1.0);
    double xx = g_acc[0] / denom;
    double yy = g_acc[1] / denom;
    double xy = (0.5 * g_acc[2] - g_acc[3]) / denom;
    out[0] = (float)(xx - 2.0 * xy + yy);
}

// ---------------- launch ----------------
extern "C" void kernel_launch(void* const* d_in, const int* in_sizes, int n_in,
                              void* d_out, int out_size){
    const float* Xs  = (const float*)d_in[0];
    const float* Xt  = (const float*)d_in[1];
    const float* W1  = (const float*)d_in[2];
    const float* b1  = (const float*)d_in[3];
    const float* W2  = (const float*)d_in[4];
    const float* b2  = (const float*)d_in[5];
    const float* W3  = (const float*)d_in[6];
    const float* b3  = (const float*)d_in[7];
    const float* W4  = (const float*)d_in[8];
    const float* b4  = (const float*)d_in[9];
    const float* eps = (const float*)d_in[10];
    const float* sg  = (const float*)d_in[11];
    const float* sg0 = (const float*)d_in[12];

    init_kernel<<<1, 32>>>(eps, sg, sg0);
    feat_kernel<<<NROWS/8, 256>>>(Xs, Xt, W1, b1, W2, b2, W3, b3, W4, b4);

    cudaFuncSetAttribute(pair_kernel, cudaFuncAttributeMaxDynamicSharedMemorySize, SMEM_BYTES);
    dim3 grid(NB, NB);
    pair_kernel<<<grid, 256, SMEM_BYTES>>>();

    fin_kernel<<<1, 1>>>((float*)d_out);
}

// round 11
// speedup vs baseline: 1.9014x; 1.1059x over previous
#include <cuda_runtime.h>
#include <cuda_bf16.h>
#include <cuda_fp16.h>
#include <math.h>
#include <stdint.h>

#define NROWS 8192
#define NHALF 4096
#define DIN   512
#define DF    64      // feature dim padded (50 -> 64, zeros)
#define DOUT  50
#define HID   10
#define BM    128
#define BN    128
#define KC    64      // phase-1 k-chunk (bf16 elements; 128 B/row)
#define NB    (NROWS/BM)   // 64
#define NPAIR (NB*(NB+1)/2)  // 2080 upper-triangle tiles
#define NCHUNK (DIN/KC)    // 8
#define LDEH  130     // Et fp16 lead dim (halves)

// smem float offsets (same as R10 layout)
#define OFF_A0  0
#define OFF_B0  4096
#define OFF_A1  8192
#define OFF_B1  12288
#define OFF_ET16 16384
#define SMEM_FLOATS (OFF_ET16 + (BM*LDEH)/2)   // 24704
#define SMEM_BYTES  (SMEM_FLOATS * 4)          // 98,816 B -> 2 CTAs/SM

// -------- scratch (no dynamic allocation allowed) --------
__device__ __nv_bfloat16 g_XcatH[NROWS*DIN];  // bf16-rounded concat(Xs,Xt)
__device__ float  g_FeaT[DF*NROWS];      // TRANSPOSED features [k][row], fp32
__device__ float  g_onorm[NROWS];        // norms of bf16-ROUNDED originals
__device__ float  g_fnorm[NROWS];
__device__ double g_acc[4];              // Sx, Sy, Smixed(2*sumKxy), Sdiag_xy
__device__ float  g_par[3];              // ep, 1/sigma, 1/sigma0

__device__ __forceinline__ float softplus_f(float x){
    return fmaxf(x, 0.f) + log1pf(expf(-fabsf(x)));
}

// exp(-x) for x >= 0, FMA-pipe only (no MUFU). ~3e-7 relative error.
__device__ __forceinline__ float exp_neg(float x){
    float t = x * -1.4426950408889634f;
    t = fmaxf(t, -125.f);
    float fn = t + 12582912.f;                   // 2^23 + 2^22 round magic
    int   ni = __float_as_int(fn) - 0x4B400000;
    float r  = t - (fn - 12582912.f);
    float p  = 1.5403530393e-4f;
    p = fmaf(p, r, 1.3333558146e-3f);
    p = fmaf(p, r, 9.6181291076e-3f);
    p = fmaf(p, r, 5.5504108665e-2f);
    p = fmaf(p, r, 2.4022650696e-1f);
    p = fmaf(p, r, 6.9314718056e-1f);
    p = fmaf(p, r, 1.0f);
    return __int_as_float(__float_as_int(p) + (ni << 23));
}

__device__ __forceinline__ void cp16(float* dst, const void* src){
    uint32_t d = (uint32_t)__cvta_generic_to_shared(dst);
    asm volatile("cp.async.cg.shared.global [%0], [%1], 16;\n"
                 :: "r"(d), "l"(src) : "memory");
}
__device__ __forceinline__ void cp_commit(){
    asm volatile("cp.async.commit_group;\n" ::: "memory");
}
__device__ __forceinline__ void ldsm4(uint32_t& r0, uint32_t& r1,
                                      uint32_t& r2, uint32_t& r3, uint32_t addr){
    asm volatile("ldmatrix.sync.aligned.m8n8.x4.shared.b16 {%0,%1,%2,%3}, [%4];"
                 : "=r"(r0), "=r"(r1), "=r"(r2), "=r"(r3) : "r"(addr));
}

// ---------------- init ----------------
__global__ void init_kernel(const float* __restrict__ eps,
                            const float* __restrict__ sig,
                            const float* __restrict__ sig0){
    if (threadIdx.x == 0){
        g_par[0] = 1.f / (1.f + expf(-eps[0]));
        g_par[1] = 1.f / (sig[0]  * sig[0]);
        g_par[2] = 1.f / (sig0[0] * sig0[0]);
        g_acc[0] = 0.0; g_acc[1] = 0.0; g_acc[2] = 0.0; g_acc[3] = 0.0;
    }
}

// ---------------- featurize: warp per row ----------------
__global__ __launch_bounds__(256)
void feat_kernel(const float* __restrict__ Xs, const float* __restrict__ Xt,
                 const float* __restrict__ W1, const float* __restrict__ b1,
                 const float* __restrict__ W2, const float* __restrict__ b2,
                 const float* __restrict__ W3, const float* __restrict__ b3,
                 const float* __restrict__ W4, const float* __restrict__ b4)
{
    __shared__ float sW1[DIN*HID];
    __shared__ float sW2[HID*HID], sW3[HID*HID], sW4[HID*DOUT];
    __shared__ float sb1[HID], sb2[HID], sb3[HID], sb4[DOUT];
    int tid = threadIdx.x;
    for (int i = tid; i < DIN*HID; i += 256) sW1[i] = W1[i];
    for (int i = tid; i < HID*HID; i += 256){ sW2[i] = W2[i]; sW3[i] = W3[i]; }
    for (int i = tid; i < HID*DOUT; i += 256) sW4[i] = W4[i];
    if (tid < HID){ sb1[tid] = b1[tid]; sb2[tid] = b2[tid]; sb3[tid] = b3[tid]; }
    if (tid < DOUT) sb4[tid] = b4[tid];
    __syncthreads();

    int warp = tid >> 5, lane = tid & 31;
    int row = blockIdx.x * 8 + warp;
    if (row >= NROWS) return;
    const float* src = (row < NHALF) ? (Xs + (size_t)row * DIN)
                                     : (Xt + (size_t)(row - NHALF) * DIN);
    float acc[HID];
    #pragma unroll
    for (int o = 0; o < HID; o++) acc[o] = 0.f;
    float on = 0.f;
    for (int k = lane; k < DIN; k += 32){
        float x = src[k];
        __nv_bfloat16 xb = __float2bfloat16_rn(x);   // round ONCE; Do exact-for-perturbed
        float xf = __bfloat162float(xb);
        g_XcatH[(size_t)row * DIN + k] = xb;
        on += xf * xf;
        #pragma unroll
        for (int o = 0; o < HID; o++) acc[o] += x * sW1[k*HID + o];
    }
    #pragma unroll
    for (int off = 16; off; off >>= 1){
        on += __shfl_xor_sync(0xffffffffu, on, off);
        #pragma unroll
        for (int o = 0; o < HID; o++)
            acc[o] += __shfl_xor_sync(0xffffffffu, acc[o], off);
    }
    if (lane == 0) g_onorm[row] = on;

    float h1[HID], h2[HID], h3[HID];
    #pragma unroll
    for (int o = 0; o < HID; o++) h1[o] = softplus_f(acc[o] + sb1[o]);
    #pragma unroll
    for (int o = 0; o < HID; o++){
        float t = sb2[o];
        #pragma unroll
        for (int p = 0; p < HID; p++) t += h1[p] * sW2[p*HID + o];
        h2[o] = softplus_f(t);
    }
    #pragma unroll
    for (int o = 0; o < HID; o++){
        float t = sb3[o];
        #pragma unroll
        for (int p = 0; p < HID; p++) t += h2[p] * sW3[p*HID + o];
        h3[o] = softplus_f(t);
    }
    float fn = 0.f;
    for (int c = lane; c < DF; c += 32){
        float v = 0.f;
        if (c < DOUT){
            v = sb4[c];
            #pragma unroll
            for (int p = 0; p < HID; p++) v += h3[p] * sW4[p*DOUT + c];
        }
        g_FeaT[(size_t)c * NROWS + row] = v;       // transposed for phase-2 cp.async
        fn += v * v;
    }
    #pragma unroll
    for (int off = 16; off; off >>= 1)
        fn += __shfl_xor_sync(0xffffffffu, fn, off);
    if (lane == 0) g_fnorm[row] = fn;
}

// ---------------- fused pairwise kernel (packed triangular grid) ----------------
__global__ __launch_bounds__(256, 2)
void pair_kernel(){
    // decode linear block id -> (bi, bj), bj >= bi
    int t = blockIdx.x;
    float nf = (float)NB + 0.5f;
    int bi = (int)(nf - sqrtf(fmaxf(nf*nf - 2.0f*(float)t, 0.f)));
    bi = max(0, min(NB - 1, bi));
    while (bi > 0 && (bi*NB - bi*(bi-1)/2) > t) bi--;
    while (((bi+1)*NB - (bi+1)*bi/2) <= t) bi++;
    int bj = bi + (t - (bi*NB - bi*(bi-1)/2));

    extern __shared__ float smem[];
    const int tid  = threadIdx.x;
    const int lane = tid & 31, warp = tid >> 5;
    const int gid  = lane >> 2, tig = lane & 3;
    const int warpM = warp >> 1, warpN = warp & 1;   // 4 x 2 warp grid
    const int rw = warpM * 32;                 // warp row base (local)
    const int cw = warpN * 64;                 // warp col base (local)
    const int rowBase = bi * BM, colBase = bj * BN;

    // ldmatrix per-thread addressing constants
    const uint32_t smem_sh = (uint32_t)__cvta_generic_to_shared(smem);
    const int msel = lane >> 3, row8 = lane & 7;
    const int aGh = msel >> 1;                 // A: mats [m0-7 g0][m8-15 g0][m0-7 g1][m8-15 g1]
    const int bGh = msel & 1;                  // B: mats [n0 g0][n0 g1][n1 g0][n1 g1]
    uint32_t aRow[2], bRow[4];
    #pragma unroll
    for (int mi = 0; mi < 2; mi++)
        aRow[mi] = (uint32_t)(rw + mi*16 + (msel & 1)*8 + row8) * 128u;
    #pragma unroll
    for (int np = 0; np < 4; np++)
        bRow[np] = (uint32_t)(cw + (2*np + (msel >> 1))*8 + row8) * 128u;

    // ---- phase 1: original-space Gram via bf16 m16n8k16 (K = 512) ----
    float acc[2][8][4];
    #pragma unroll
    for (int mi = 0; mi < 2; mi++)
        #pragma unroll
        for (int ni = 0; ni < 8; ni++)
            #pragma unroll
            for (int r = 0; r < 4; r++) acc[mi][ni][r] = 0.f;

    #pragma unroll
    for (int st = 0; st < 2; st++){
        float* bA = smem + (st ? OFF_A1 : OFF_A0);
        float* bB = smem + (st ? OFF_B1 : OFF_B0);
        int kb = st * KC;
        #pragma unroll
        for (int i = 0; i < 4; i++){
            int idx = tid + i * 256;
            int r = idx >> 3, g = idx & 7;
            int sw = r*32 + (((g ^ (r & 7)) << 2));
            cp16(bA + sw, &g_XcatH[(size_t)(rowBase + r)*DIN + kb + (g << 3)]);
            cp16(bB + sw, &g_XcatH[(size_t)(colBase + r)*DIN + kb + (g << 3)]);
        }
        cp_commit();
    }

    for (int c = 0; c < NCHUNK; c++){
        if (c < NCHUNK - 1) asm volatile("cp.async.wait_group 1;\n" ::: "memory");
        else                asm volatile("cp.async.wait_group 0;\n" ::: "memory");
        __syncthreads();

        const uint32_t baseA = smem_sh + ((c & 1) ? OFF_A1 : OFF_A0) * 4u;
        const uint32_t baseB = smem_sh + ((c & 1) ? OFF_B1 : OFF_B0) * 4u;

        #pragma unroll
        for (int ks = 0; ks < 4; ks++){        // 4 k16-steps per 64-elem chunk
            const int g0 = 2*ks;
            uint32_t a[2][4];
            #pragma unroll
            for (int mi = 0; mi < 2; mi++){
                uint32_t ad = baseA + aRow[mi] + ((uint32_t)((g0 + aGh) ^ row8) << 4);
                ldsm4(a[mi][0], a[mi][1], a[mi][2], a[mi][3], ad);
            }
            uint32_t bfr[8][2];
            #pragma unroll
            for (int np = 0; np < 4; np++){
                uint32_t ad = baseB + bRow[np] + ((uint32_t)((g0 + bGh) ^ row8) << 4);
                ldsm4(bfr[2*np][0], bfr[2*np][1], bfr[2*np+1][0], bfr[2*np+1][1], ad);
            }
            #pragma unroll
            for (int mi = 0; mi < 2; mi++)
                #pragma unroll
                for (int ni = 0; ni < 8; ni++){
                    asm volatile(
                        "mma.sync.aligned.m16n8k16.row.col.f32.bf16.bf16.f32 "
                        "{%0,%1,%2,%3}, {%4,%5,%6,%7}, {%8,%9}, {%0,%1,%2,%3};\n"
                        : "+f"(acc[mi][ni][0]), "+f"(acc[mi][ni][1]),
                          "+f"(acc[mi][ni][2]), "+f"(acc[mi][ni][3])
                        : "r"(a[mi][0]), "r"(a[mi][1]), "r"(a[mi][2]), "r"(a[mi][3]),
                          "r"(bfr[ni][0]), "r"(bfr[ni][1]));
                }
        }
        __syncthreads();     // all warps done reading buf[c&1] before refill

        if (c + 2 < NCHUNK){
            float* bA = smem + ((c & 1) ? OFF_A1 : OFF_A0);
            float* bB = smem + ((c & 1) ? OFF_B1 : OFF_B0);
            int kb = (c + 2) * KC;
            #pragma unroll
            for (int i = 0; i < 4; i++){
                int idx = tid + i * 256;
                int r = idx >> 3, g = idx & 7;
                int sw = r*32 + (((g ^ (r & 7)) << 2));
                cp16(bA + sw, &g_XcatH[(size_t)(rowBase + r)*DIN + kb + (g << 3)]);
                cp16(bB + sw, &g_XcatH[(size_t)(colBase + r)*DIN + kb + (g << 3)]);
            }
            cp_commit();
        }
    }
    // All phase-1 buffers dead now.

    // Prefetch BOTH transposed Fea tiles into [0,16384) floats (overlaps Et epilogue).
    #pragma unroll
    for (int i = 0; i < 8; i++){
        int idx = tid + i * 256;
        int k = idx >> 5, gr = (idx & 31) << 2;
        cp16(smem + k*128 + gr,        &g_FeaT[(size_t)k*NROWS + rowBase + gr]);
        cp16(smem + 8192 + k*128 + gr, &g_FeaT[(size_t)k*NROWS + colBase + gr]);
    }
    cp_commit();

    const float ep    = g_par[0];
    const float invs  = g_par[1];
    const float invs0 = g_par[2];
    __half* Et16 = (__half*)(smem + OFF_ET16); // [128][LDEH] halves

    {   // phase-1 epilogue: Do -> e_org, stage into Et16 (fragment -> (row,col))
        float rn[4], cn[16];
        #pragma unroll
        for (int mi = 0; mi < 2; mi++)
            #pragma unroll
            for (int rr = 0; rr < 2; rr++)
                rn[mi*2+rr] = g_onorm[rowBase + rw + mi*16 + rr*8 + gid];
        #pragma unroll
        for (int ni = 0; ni < 8; ni++)
            #pragma unroll
            for (int cc = 0; cc < 2; cc++)
                cn[ni*2+cc] = g_onorm[colBase + cw + ni*8 + tig*2 + cc];
        #pragma unroll
        for (int mi = 0; mi < 2; mi++)
            #pragma unroll
            for (int ni = 0; ni < 8; ni++)
                #pragma unroll
                for (int rr = 0; rr < 2; rr++)
                    #pragma unroll
                    for (int cc = 0; cc < 2; cc++){
                        int lm = rw + mi*16 + rr*8 + gid;
                        int ln = cw + ni*8 + tig*2 + cc;
                        float d = fmaxf(rn[mi*2+rr] + cn[ni*2+cc]
                                        - 2.f * acc[mi][ni][rr*2+cc], 0.f);
                        Et16[lm*LDEH + ln] = __float2half(exp_neg(d * invs));
                    }
    }

    asm volatile("cp.async.wait_group 0;\n" ::: "memory");
    __syncthreads();                           // Fea tiles + Et16 visible

    // ---- phase 2: feature Gram, fp32 SIMT (RN accumulate — bias-free) ----
    const float* FAt = smem;                   // [64][128]
    const float* FBt = smem + 8192;            // [64][128]
    const int tx = tid & 15, ty = tid >> 4;

    float fac[8][8];
    #pragma unroll
    for (int m = 0; m < 8; m++)
        #pragma unroll
        for (int n = 0; n < 8; n++) fac[m][n] = 0.f;

    for (int kb = 0; kb < DF; kb += 16){
        #pragma unroll
        for (int k16 = 0; k16 < 16; k16++){
            const int k = kb + k16;
            float a[8], b[8];
            #pragma unroll
            for (int m = 0; m < 8; m++) a[m] = FAt[k*128 + ty*8 + m];
            #pragma unroll
            for (int n = 0; n < 8; n++) b[n] = FBt[k*128 + tx*8 + n];
            #pragma unroll
            for (int m = 0; m < 8; m++)
                #pragma unroll
                for (int n = 0; n < 8; n++) fac[m][n] += a[m] * b[n];
        }
    }

    // ---- final epilogue: per-TILE classification (NHALF = 32 tiles exactly) ----
    // bj >= bi always. bj < 32 -> both X; bi >= 32 -> both Y; else mixed.
    const bool diagTile = (bi == bj);
    const bool sdTile   = (bj - bi == 32);     // ci - ri == NHALF  <=>  ln == lm
    const int  cls      = (bj < 32) ? 0 : ((bi >= 32) ? 1 : 2);
    const float mult    = diagTile ? 1.f : 2.f;

    float fnr[8], fnc[8];
    #pragma unroll
    for (int m = 0; m < 8; m++) fnr[m] = g_fnorm[rowBase + ty*8 + m];
    #pragma unroll
    for (int n = 0; n < 8; n++) fnc[n] = g_fnorm[colBase + tx*8 + n];

    float s = 0.f, sd = 0.f;
    #pragma unroll
    for (int m = 0; m < 8; m++){
        const int lm = ty*8 + m;
        #pragma unroll
        for (int n = 0; n < 8; n++){
            const int ln = tx*8 + n;
            if (diagTile && lm == ln) continue;          // diagonal excluded
            float dd = fmaxf(fnr[m] + fnc[n] - 2.f * fac[m][n], 0.f);
            float eo = __half2float(Et16[lm*LDEH + ln]);
            float kv = (1.f - ep) * exp_neg(dd * invs0) * eo + ep * eo;
            s += kv;
            if (sdTile && lm == ln) sd += kv;
        }
    }
    s *= mult;                                  // sd counted once per pair

    #pragma unroll
    for (int off = 16; off; off >>= 1)
        s += __shfl_xor_sync(0xffffffffu, s, off);
    if (sdTile){
        #pragma unroll
        for (int off = 16; off; off >>= 1)
            sd += __shfl_xor_sync(0xffffffffu, sd, off);
    }
    if (lane == 0){
        atomicAdd(&g_acc[cls], (double)s);
        if (sdTile) atomicAdd(&g_acc[3], (double)sd);
    }
}

// ---------------- finalize ----------------
__global__ void fin_kernel(float* __restrict__ out){
    double n = (double)NHALF;
    double denom = n * (n - 1.0);
    double xx = g_acc[0] / denom;
    double yy = g_acc[1] / denom;
    double xy = (0.5 * g_acc[2] - g_acc[3]) / denom;
    out[0] = (float)(xx - 2.0 * xy + yy);
}

// ---------------- launch ----------------
extern "C" void kernel_launch(void* const* d_in, const int* in_sizes, int n_in,
                              void* d_out, int out_size){
    const float* Xs  = (const float*)d_in[0];
    const float* Xt  = (const float*)d_in[1];
    const float* W1  = (const float*)d_in[2];
    const float* b1  = (const float*)d_in[3];
    const float* W2  = (const float*)d_in[4];
    const float* b2  = (const float*)d_in[5];
    const float* W3  = (const float*)d_in[6];
    const float* b3  = (const float*)d_in[7];
    const float* W4  = (const float*)d_in[8];
    const float* b4  = (const float*)d_in[9];
    const float* eps = (const float*)d_in[10];
    const float* sg  = (const float*)d_in[11];
    const float* sg0 = (const float*)d_in[12];

    init_kernel<<<1, 32>>>(eps, sg, sg0);
    feat_kernel<<<NROWS/8, 256>>>(Xs, Xt, W1, b1, W2, b2, W3, b3, W4, b4);

    cudaFuncSetAttribute(pair_kernel, cudaFuncAttributeMaxDynamicSharedMemorySize, SMEM_BYTES);
    pair_kernel<<<NPAIR, 256, SMEM_BYTES>>>();

    fin_kernel<<<1, 1>>>((float*)d_out);
}